// round 1
// baseline (speedup 1.0000x reference)
#include <cuda_runtime.h>
#include <cuda_bf16.h>
#include <math.h>

// ---------------- problem constants ----------------
#define BB        2
#define SS        4096
#define HH        2048
#define NHEADS    16
#define HDIM      128
#define KSEL      128
#define NROWS     (BB*SS)            // 8192
#define NBH       (BB*NHEADS)        // 32
#define ROWHID    ((long)NROWS*HH)   // 16777216

// ---------------- scratch (device globals; no allocs allowed) ----------------
__device__ float gQ[ROWHID];
__device__ float gK[ROWHID];
__device__ float gV[ROWHID];
__device__ float gTmp[ROWHID];   // reused: score-net hidden, then attn scores/probs
__device__ float gO[ROWHID];     // attention output in [B,S,H] layout
__device__ float gScores[NBH*SS];       // kv_scores
__device__ int   gIdx[NBH*KSEL];        // selected key indices
__device__ float gKsel[NBH*KSEL*HDIM];  // [bh][j][d]
__device__ float gVselT[NBH*KSEL*HDIM]; // [bh][d][j]  (transposed for NT gemm)

// ---------------- generic batched SGEMM: C = alpha * A * B^T ----------------
// A: M x Kd (row-major, lda), B: N x Kd (row-major, ldb), C: M x N (ldc).
// Batch via blockIdx.z: bb = z>>4, hh = z&15; base += bb*s?b + hh*s?h.
#define TS 64
#define KT 16
__global__ __launch_bounds__(256) void sgemm_nt(
    const float* __restrict__ A, int lda, long sAb, long sAh,
    const float* __restrict__ B, int ldb, long sBb, long sBh,
    float*       __restrict__ C, int ldc, long sCb, long sCh,
    int M, int N, int Kd, float alpha)
{
    int z  = blockIdx.z;
    int zb = z >> 4, zh = z & 15;
    A += zb * sAb + zh * sAh;
    B += zb * sBb + zh * sBh;
    C += zb * sCb + zh * sCh;

    __shared__ float As[KT][TS + 4];
    __shared__ float Bs[KT][TS + 4];

    int t  = threadIdx.x;          // 0..255
    int tx = t & 15;               // col group
    int ty = t >> 4;               // row group
    long m0 = (long)blockIdx.y * TS;
    long n0 = (long)blockIdx.x * TS;

    float acc[4][4];
#pragma unroll
    for (int i = 0; i < 4; i++)
#pragma unroll
        for (int j = 0; j < 4; j++) acc[i][j] = 0.f;

    for (int kk = 0; kk < Kd; kk += KT) {
        // load 64x16 tiles of A and B (kq fastest -> coalesced global reads)
#pragma unroll
        for (int r = 0; r < 4; r++) {
            int e  = t + r * 256;
            int mm = e >> 4;
            int kq = e & 15;
            As[kq][mm] = A[(m0 + mm) * lda + kk + kq];
            Bs[kq][mm] = B[(n0 + mm) * ldb + kk + kq];
        }
        __syncthreads();
#pragma unroll
        for (int kq = 0; kq < KT; kq++) {
            float a[4], b[4];
#pragma unroll
            for (int i = 0; i < 4; i++) a[i] = As[kq][ty * 4 + i];
#pragma unroll
            for (int j = 0; j < 4; j++) b[j] = Bs[kq][tx * 4 + j];
#pragma unroll
            for (int i = 0; i < 4; i++)
#pragma unroll
                for (int j = 0; j < 4; j++) acc[i][j] += a[i] * b[j];
        }
        __syncthreads();
    }
#pragma unroll
    for (int i = 0; i < 4; i++)
#pragma unroll
        for (int j = 0; j < 4; j++)
            C[(m0 + ty * 4 + i) * ldc + n0 + tx * 4 + j] = alpha * acc[i][j];
}

// ---------------- score-net stage 2: relu(hidden+sb1) . sw2 + sb2 ----------------
// hidden rows: 131072 x 128. One warp per row.
__global__ void score_stage2(const float* __restrict__ hidden,
                             const float* __restrict__ sb1,
                             const float* __restrict__ sw2,
                             const float* __restrict__ sb2,
                             float* __restrict__ out, int nrows)
{
    int warp = (blockIdx.x * blockDim.x + threadIdx.x) >> 5;
    int lane = threadIdx.x & 31;
    if (warp >= nrows) return;
    const float4 hv = ((const float4*)(hidden + (long)warp * 128))[lane];
    const float4 b1 = ((const float4*)sb1)[lane];
    const float4 w2 = ((const float4*)sw2)[lane];
    float s = fmaxf(hv.x + b1.x, 0.f) * w2.x
            + fmaxf(hv.y + b1.y, 0.f) * w2.y
            + fmaxf(hv.z + b1.z, 0.f) * w2.z
            + fmaxf(hv.w + b1.w, 0.f) * w2.w;
#pragma unroll
    for (int o = 16; o > 0; o >>= 1) s += __shfl_xor_sync(0xFFFFFFFFu, s, o);
    if (lane == 0) out[warp] = s + sb2[0];
}

// ---------------- sparsek projection + exact top-128 selection ----------------
// One block per (b,h). Bitonic sort 4096 (value desc, index asc), then the
// exact reference recipe: rho = count(s_r > (cs_r - K)/(r+1)); tau from
// cs[rho-1]; npos = count(s > tau); take top-npos (capped 128) sorted indices,
// fill remaining (rho<128 path) with smallest non-support indices.
__device__ __forceinline__ unsigned enc_desc(float v) {
    unsigned b = __float_as_uint(v);
    unsigned o = (b & 0x80000000u) ? ~b : (b | 0x80000000u); // ascending-ordered
    return ~o;                                               // descending
}
__device__ __forceinline__ float dec_desc(unsigned d) {
    unsigned o = ~d;
    unsigned b = (o & 0x80000000u) ? (o ^ 0x80000000u) : ~o;
    return __uint_as_float(b);
}

__global__ __launch_bounds__(1024) void sparsek_topk(const float* __restrict__ scores,
                                                     int* __restrict__ out_idx)
{
    __shared__ unsigned long long key[SS];
    __shared__ unsigned char flag[SS];
    __shared__ int nposs;
    int bh  = blockIdx.x;
    int tid = threadIdx.x;
    const float* s = scores + (long)bh * SS;

    for (int i = tid; i < SS; i += 1024)
        key[i] = ((unsigned long long)enc_desc(s[i]) << 32) | (unsigned)i;
    __syncthreads();

    for (int k = 2; k <= SS; k <<= 1) {
        for (int j = k >> 1; j > 0; j >>= 1) {
            for (int i = tid; i < SS; i += 1024) {
                int ixj = i ^ j;
                if (ixj > i) {
                    bool up = ((i & k) == 0);
                    unsigned long long a = key[i], b = key[ixj];
                    if ((a > b) == up) { key[i] = b; key[ixj] = a; }
                }
            }
            __syncthreads();
        }
    }
    // key now ascending  ==  value descending, index ascending on ties.

    if (tid == 0) {
        float cs = 0.f;
        int rho = 0;
        for (int r = 0; r < SS; r++) {
            float v = dec_desc((unsigned)(key[r] >> 32));
            cs += v;
            float thr = (cs - (float)KSEL) / (float)(r + 1);
            if (v > thr) rho++;
        }
        if (rho < 1) rho = 1;
        float cs2 = 0.f;
        for (int r = 0; r < rho; r++) cs2 += dec_desc((unsigned)(key[r] >> 32));
        float tau = (cs2 - (float)KSEL) / (float)rho;
        int npos = 0;
        for (int r = 0; r < SS; r++)
            if (dec_desc((unsigned)(key[r] >> 32)) > tau) npos++;
        nposs = npos;
    }
    __syncthreads();

    int npos = nposs;
    if (npos >= KSEL) {
        if (tid < KSEL)
            out_idx[bh * KSEL + tid] = (int)(key[tid] & 0xFFFFFFFFu);
    } else {
        // rare path: all positives, then smallest-index zeros (top_k tie rule)
        if (tid < npos)
            out_idx[bh * KSEL + tid] = (int)(key[tid] & 0xFFFFFFFFu);
        for (int i = tid; i < SS; i += 1024) flag[i] = 0;
        __syncthreads();
        for (int i = tid; i < npos; i += 1024)
            flag[key[i] & 0xFFFFFFFFu] = 1;
        __syncthreads();
        if (tid == 0) {
            int cnt = npos;
            for (int i = 0; i < SS && cnt < KSEL; i++)
                if (!flag[i]) out_idx[bh * KSEL + cnt++] = i;
        }
    }
}

// ---------------- gather selected K rows (and V transposed) ----------------
__global__ void gather_kv(const float* __restrict__ Kg, const float* __restrict__ Vg,
                          const int* __restrict__ idx,
                          float* __restrict__ ksel, float* __restrict__ vselT)
{
    int bh = blockIdx.x >> 7;   // 0..31
    int j  = blockIdx.x & 127;  // 0..127
    int d  = threadIdx.x;       // 0..127
    int b  = bh >> 4, h = bh & 15;
    int row = idx[bh * KSEL + j];
    long src = ((long)(b * SS + row)) * HH + (long)h * HDIM + d;
    ksel [(long)bh * (KSEL*HDIM) + (long)j * HDIM + d] = Kg[src];
    vselT[(long)bh * (KSEL*HDIM) + (long)d * KSEL + j] = Vg[src];
}

// ---------------- softmax over rows of 128 ----------------
__global__ void softmax128(float* __restrict__ p, int nrows)
{
    int warp = (blockIdx.x * blockDim.x + threadIdx.x) >> 5;
    int lane = threadIdx.x & 31;
    if (warp >= nrows) return;
    float4* row = (float4*)(p + (long)warp * 128);
    float4 v = row[lane];
    float m = fmaxf(fmaxf(v.x, v.y), fmaxf(v.z, v.w));
#pragma unroll
    for (int o = 16; o > 0; o >>= 1) m = fmaxf(m, __shfl_xor_sync(0xFFFFFFFFu, m, o));
    v.x = expf(v.x - m); v.y = expf(v.y - m);
    v.z = expf(v.z - m); v.w = expf(v.w - m);
    float sum = v.x + v.y + v.z + v.w;
#pragma unroll
    for (int o = 16; o > 0; o >>= 1) sum += __shfl_xor_sync(0xFFFFFFFFu, sum, o);
    float inv = 1.0f / sum;
    v.x *= inv; v.y *= inv; v.z *= inv; v.w *= inv;
    row[lane] = v;
}

// ---------------- launch ----------------
extern "C" void kernel_launch(void* const* d_in, const int* in_sizes, int n_in,
                              void* d_out, int out_size)
{
    const float* x   = (const float*)d_in[0];
    const float* wq  = (const float*)d_in[1];
    const float* wk  = (const float*)d_in[2];
    const float* wv  = (const float*)d_in[3];
    const float* wo  = (const float*)d_in[4];
    const float* sw1 = (const float*)d_in[5];
    const float* sb1 = (const float*)d_in[6];
    const float* sw2 = (const float*)d_in[7];
    const float* sb2 = (const float*)d_in[8];
    float* out = (float*)d_out;

    float *pQ, *pK, *pV, *pTmp, *pO, *pScores, *pKsel, *pVselT;
    int* pIdx;
    cudaGetSymbolAddress((void**)&pQ,      gQ);
    cudaGetSymbolAddress((void**)&pK,      gK);
    cudaGetSymbolAddress((void**)&pV,      gV);
    cudaGetSymbolAddress((void**)&pTmp,    gTmp);
    cudaGetSymbolAddress((void**)&pO,      gO);
    cudaGetSymbolAddress((void**)&pScores, gScores);
    cudaGetSymbolAddress((void**)&pIdx,    gIdx);
    cudaGetSymbolAddress((void**)&pKsel,   gKsel);
    cudaGetSymbolAddress((void**)&pVselT,  gVselT);

    const long sBH  = (long)SS * HH;        // 8388608  per-batch stride in [B,S,H]
    const long sHd  = HDIM;                 // per-head column offset
    const long sTb  = (long)NHEADS * SS * HDIM; // 8388608 per-batch in [b][h][s][128]
    const long sTh  = (long)SS * HDIM;          // 524288  per-head
    const long sSelb = (long)NHEADS * KSEL * HDIM; // 262144
    const long sSelh = (long)KSEL * HDIM;          // 16384

    dim3 gproj(HH / TS, NROWS / TS, 1);   // (32,128,1)
    dim3 gatt (HDIM / TS, SS / TS, NBH);  // (2,64,32)

    // 1-3. Q, K, V projections
    sgemm_nt<<<gproj, 256>>>(x, HH, 0, 0, wq, HH, 0, 0, pQ, HH, 0, 0, NROWS, HH, HH, 1.0f);
    sgemm_nt<<<gproj, 256>>>(x, HH, 0, 0, wk, HH, 0, 0, pK, HH, 0, 0, NROWS, HH, HH, 1.0f);
    sgemm_nt<<<gproj, 256>>>(x, HH, 0, 0, wv, HH, 0, 0, pV, HH, 0, 0, NROWS, HH, HH, 1.0f);

    // 4. score-net hidden = K_head @ sw1^T   (per (b,h))
    sgemm_nt<<<gatt, 256>>>(pK, HH, sBH, sHd,
                            sw1, HDIM, 0, 0,
                            pTmp, HDIM, sTb, sTh,
                            SS, HDIM, HDIM, 1.0f);

    // 5. kv_scores
    score_stage2<<<(NBH * SS) / 8, 256>>>(pTmp, sb1, sw2, sb2, pScores, NBH * SS);

    // 6. sparsek + top-128
    sparsek_topk<<<NBH, 1024>>>(pScores, pIdx);

    // 7. gather selected K / V^T
    gather_kv<<<NBH * KSEL, HDIM>>>(pK, pV, pIdx, pKsel, pVselT);

    // 8. attn scores = Q_head @ Ksel^T * scale
    const float scale = 0.08838834764831845f; // 1/sqrt(128)
    sgemm_nt<<<gatt, 256>>>(pQ, HH, sBH, sHd,
                            pKsel, HDIM, sSelb, sSelh,
                            pTmp, HDIM, sTb, sTh,
                            SS, KSEL, HDIM, scale);

    // 9. softmax rows of 128
    softmax128<<<(NBH * SS) / 8, 256>>>(pTmp, NBH * SS);

    // 10. out_head = P @ Vsel  (NT against VselT), written into [B,S,H] layout
    sgemm_nt<<<gatt, 256>>>(pTmp, HDIM, sTb, sTh,
                            pVselT, KSEL, sSelb, sSelh,
                            pO, HH, sBH, sHd,
                            SS, HDIM, KSEL, 1.0f);

    // 11. final projection: out = O @ wo^T
    sgemm_nt<<<gproj, 256>>>(pO, HH, 0, 0, wo, HH, 0, 0, out, HH, 0, 0, NROWS, HH, HH, 1.0f);
}

// round 3
// speedup vs baseline: 2.3810x; 2.3810x over previous
#include <cuda_runtime.h>
#include <cuda_fp16.h>
#include <math.h>
#include <stdint.h>

// ---------------- problem constants ----------------
#define BB        2
#define SS        4096
#define HH        2048
#define NHEADS    16
#define HDIM      128
#define KSEL      128
#define NROWS     (BB*SS)            // 8192
#define NBH       (BB*NHEADS)        // 32
#define ROWHID    ((long)NROWS*HH)   // 16777216
#define WN        ((long)HH*HH)      // 4194304

// ---------------- scratch (device globals; no allocs allowed) ----------------
__device__ float gQ[ROWHID];
__device__ float gK[ROWHID];
__device__ float gV[ROWHID];
__device__ float gTmp[ROWHID];
__device__ float gO[ROWHID];
__device__ float gScores[NBH*SS];
__device__ int   gIdx[NBH*KSEL];
__device__ float gKsel[NBH*KSEL*HDIM];
__device__ float gVselT[NBH*KSEL*HDIM];
// fp16 split buffers
__device__ __half gXhi[ROWHID];
__device__ __half gXlo[ROWHID];
__device__ __half gWhi[WN];
__device__ __half gWlo[WN];

// =================== helpers ===================
__device__ __forceinline__ uint32_t smem_u32(const void* p) {
    uint32_t a;
    asm("{ .reg .u64 t; cvta.to.shared.u64 t, %1; cvt.u32.u64 %0, t; }" : "=r"(a) : "l"(p));
    return a;
}
__device__ __forceinline__ void cp16(uint32_t dst, const void* src) {
    asm volatile("cp.async.cg.shared.global [%0], [%1], 16;" :: "r"(dst), "l"(src));
}
__device__ __forceinline__ void cp_commit() {
    asm volatile("cp.async.commit_group;" ::: "memory");
}
template<int N>
__device__ __forceinline__ void cp_wait() {
    asm volatile("cp.async.wait_group %0;" :: "n"(N) : "memory");
}
__device__ __forceinline__ void mma16816(float* c, const uint32_t* a, const uint32_t* b) {
    asm volatile(
        "mma.sync.aligned.m16n8k16.row.col.f32.f16.f16.f32 "
        "{%0,%1,%2,%3}, {%4,%5,%6,%7}, {%8,%9}, {%0,%1,%2,%3};"
        : "+f"(c[0]), "+f"(c[1]), "+f"(c[2]), "+f"(c[3])
        : "r"(a[0]), "r"(a[1]), "r"(a[2]), "r"(a[3]), "r"(b[0]), "r"(b[1]));
}

// =================== split: fp32 -> fp16 hi + fp16 lo*64 ===================
__global__ void split2h(const float* __restrict__ s, __half* __restrict__ hi,
                        __half* __restrict__ lo, long n)
{
    long i = (long)blockIdx.x * blockDim.x + threadIdx.x;
    if (i >= n) return;
    float x = s[i];
    __half h = __float2half_rn(x);
    float r = x - __half2float(h);
    hi[i] = h;
    lo[i] = __float2half_rn(r * 64.0f);
}

// =================== HMMA split GEMM: C = A * B^T (fp32 in/out) ===================
// A: [M,Kd] via (Ahi,Alo) fp16 planes; B: [N,Kd] via (Bhi,Blo); C: [M,N] fp32.
// CTA tile 128x128x32, 8 warps (warp tile 64x32), cp.async double buffer.
#define SKW 40                       // smem row stride in halves (bank-conflict-free)
#define PLANE_B (128 * SKW * 2)      // 10240 bytes per plane
#define STAGE_B (4 * PLANE_B)        // 40960 bytes per stage

__global__ __launch_bounds__(256, 1) void hgemm_split(
    const __half* __restrict__ Ahi, const __half* __restrict__ Alo,
    const __half* __restrict__ Bhi, const __half* __restrict__ Blo,
    float* __restrict__ C, int lda, int ldb, int ldc, int Kd)
{
    extern __shared__ char smem[];
    const uint32_t smb = smem_u32(smem);
    const int tid  = threadIdx.x;
    const int wid  = tid >> 5;
    const int lane = tid & 31;
    const int wm   = wid & 1;        // 2 warps along M
    const int wn   = wid >> 1;       // 4 warps along N
    const int qrow = lane >> 2;      // 0..7
    const int qk   = (lane & 3) * 2; // 0,2,4,6

    const long m0 = (long)blockIdx.y * 128;
    const long n0 = (long)blockIdx.x * 128;

    const __half* planes[4] = {Ahi, Alo, Bhi, Blo};
    const long pbase[4] = {m0 * lda, m0 * lda, n0 * ldb, n0 * ldb};
    const int  plld[4]  = {lda, lda, ldb, ldb};

    // per-thread load slots: 512 16B-chunks per plane stage-slice / 256 thr = 2
    const int r0 = tid >> 2, s0 = tid & 3;           // chunk tid
    const int r1 = (tid + 256) >> 2, s1 = tid & 3;   // chunk tid+256

    float acc[4][4][4];  // [mt][nt][4] main
    float axx[4][4][4];  // cross (scaled by 64)
#pragma unroll
    for (int i = 0; i < 4; i++)
#pragma unroll
        for (int j = 0; j < 4; j++)
#pragma unroll
            for (int r = 0; r < 4; r++) { acc[i][j][r] = 0.f; axx[i][j][r] = 0.f; }

    const int NC = Kd / 32;

    // ---- prologue: stage 0 ----
#pragma unroll
    for (int p = 0; p < 4; p++) {
        const __half* gp = planes[p] + pbase[p];
        const int ld = plld[p];
        cp16(smb + p * PLANE_B + r0 * (SKW * 2) + s0 * 16, gp + (long)r0 * ld + s0 * 8);
        cp16(smb + p * PLANE_B + r1 * (SKW * 2) + s1 * 16, gp + (long)r1 * ld + s1 * 8);
    }
    cp_commit();

    for (int ch = 0; ch < NC; ch++) {
        const int st = ch & 1;
        if (ch + 1 < NC) {
            const int k0 = (ch + 1) * 32;
            const uint32_t sb = smb + (st ^ 1) * STAGE_B;
#pragma unroll
            for (int p = 0; p < 4; p++) {
                const __half* gp = planes[p] + pbase[p] + k0;
                const int ld = plld[p];
                cp16(sb + p * PLANE_B + r0 * (SKW * 2) + s0 * 16, gp + (long)r0 * ld + s0 * 8);
                cp16(sb + p * PLANE_B + r1 * (SKW * 2) + s1 * 16, gp + (long)r1 * ld + s1 * 8);
            }
            cp_commit();
            cp_wait<1>();
        } else {
            cp_wait<0>();
        }
        __syncthreads();

        const uint32_t* sAh = (const uint32_t*)(smem + st * STAGE_B + 0 * PLANE_B);
        const uint32_t* sAl = (const uint32_t*)(smem + st * STAGE_B + 1 * PLANE_B);
        const uint32_t* sBh = (const uint32_t*)(smem + st * STAGE_B + 2 * PLANE_B);
        const uint32_t* sBl = (const uint32_t*)(smem + st * STAGE_B + 3 * PLANE_B);

#pragma unroll
        for (int ks = 0; ks < 2; ks++) {
            const int kb = ks * 16;
            uint32_t af[4][4], bf[4][2];
            // A hi fragments
#pragma unroll
            for (int mt = 0; mt < 4; mt++) {
                const int mr = wm * 64 + mt * 16 + qrow;
                af[mt][0] = sAh[(mr * SKW + kb + qk) >> 1];
                af[mt][1] = sAh[((mr + 8) * SKW + kb + qk) >> 1];
                af[mt][2] = sAh[(mr * SKW + kb + qk + 8) >> 1];
                af[mt][3] = sAh[((mr + 8) * SKW + kb + qk + 8) >> 1];
            }
            // B hi fragments
#pragma unroll
            for (int nt = 0; nt < 4; nt++) {
                const int nr = wn * 32 + nt * 8 + qrow;
                bf[nt][0] = sBh[(nr * SKW + kb + qk) >> 1];
                bf[nt][1] = sBh[(nr * SKW + kb + qk + 8) >> 1];
            }
            // main: hi*hi
#pragma unroll
            for (int mt = 0; mt < 4; mt++)
#pragma unroll
                for (int nt = 0; nt < 4; nt++)
                    mma16816(acc[mt][nt], af[mt], bf[nt]);
            // cross 1: hi * lo'
            uint32_t bl[4][2];
#pragma unroll
            for (int nt = 0; nt < 4; nt++) {
                const int nr = wn * 32 + nt * 8 + qrow;
                bl[nt][0] = sBl[(nr * SKW + kb + qk) >> 1];
                bl[nt][1] = sBl[(nr * SKW + kb + qk + 8) >> 1];
            }
#pragma unroll
            for (int mt = 0; mt < 4; mt++)
#pragma unroll
                for (int nt = 0; nt < 4; nt++)
                    mma16816(axx[mt][nt], af[mt], bl[nt]);
            // cross 2: lo' * hi  (reuse af regs)
#pragma unroll
            for (int mt = 0; mt < 4; mt++) {
                const int mr = wm * 64 + mt * 16 + qrow;
                af[mt][0] = sAl[(mr * SKW + kb + qk) >> 1];
                af[mt][1] = sAl[((mr + 8) * SKW + kb + qk) >> 1];
                af[mt][2] = sAl[(mr * SKW + kb + qk + 8) >> 1];
                af[mt][3] = sAl[((mr + 8) * SKW + kb + qk + 8) >> 1];
            }
#pragma unroll
            for (int mt = 0; mt < 4; mt++)
#pragma unroll
                for (int nt = 0; nt < 4; nt++)
                    mma16816(axx[mt][nt], af[mt], bf[nt]);
        }
        __syncthreads();
    }

    // ---- epilogue: fold, stage through smem, coalesced fp32 stores ----
    float* cs = (float*)smem;   // [128][132]
    const float inv64 = 1.0f / 64.0f;
#pragma unroll
    for (int mt = 0; mt < 4; mt++) {
#pragma unroll
        for (int nt = 0; nt < 4; nt++) {
            const int r = wm * 64 + mt * 16 + qrow;
            const int c = wn * 32 + nt * 8 + (lane & 3) * 2;
            cs[r * 132 + c]           = acc[mt][nt][0] + axx[mt][nt][0] * inv64;
            cs[r * 132 + c + 1]       = acc[mt][nt][1] + axx[mt][nt][1] * inv64;
            cs[(r + 8) * 132 + c]     = acc[mt][nt][2] + axx[mt][nt][2] * inv64;
            cs[(r + 8) * 132 + c + 1] = acc[mt][nt][3] + axx[mt][nt][3] * inv64;
        }
    }
    __syncthreads();
    {
        const int row = tid >> 1;
        const int half = tid & 1;
        const float4* srow = (const float4*)(cs + row * 132 + half * 64);
        float4* crow = (float4*)(C + (m0 + row) * (long)ldc + n0 + half * 64);
#pragma unroll
        for (int i = 0; i < 16; i++) crow[i] = srow[i];
    }
}

// =================== fp32 batched SGEMM (small GEMMs) ===================
#define TS 64
#define KT 16
__global__ __launch_bounds__(256) void sgemm_nt(
    const float* __restrict__ A, int lda, long sAb, long sAh,
    const float* __restrict__ B, int ldb, long sBb, long sBh,
    float*       __restrict__ C, int ldc, long sCb, long sCh,
    int M, int N, int Kd, float alpha)
{
    int z  = blockIdx.z;
    int zb = z >> 4, zh = z & 15;
    A += zb * sAb + zh * sAh;
    B += zb * sBb + zh * sBh;
    C += zb * sCb + zh * sCh;

    __shared__ float As[KT][TS + 4];
    __shared__ float Bs[KT][TS + 4];

    int t  = threadIdx.x;
    int tx = t & 15;
    int ty = t >> 4;
    long m0 = (long)blockIdx.y * TS;
    long n0 = (long)blockIdx.x * TS;

    float acc[4][4];
#pragma unroll
    for (int i = 0; i < 4; i++)
#pragma unroll
        for (int j = 0; j < 4; j++) acc[i][j] = 0.f;

    for (int kk = 0; kk < Kd; kk += KT) {
#pragma unroll
        for (int r = 0; r < 4; r++) {
            int e  = t + r * 256;
            int mm = e >> 4;
            int kq = e & 15;
            As[kq][mm] = A[(m0 + mm) * lda + kk + kq];
            Bs[kq][mm] = B[(n0 + mm) * ldb + kk + kq];
        }
        __syncthreads();
#pragma unroll
        for (int kq = 0; kq < KT; kq++) {
            float a[4], b[4];
#pragma unroll
            for (int i = 0; i < 4; i++) a[i] = As[kq][ty * 4 + i];
#pragma unroll
            for (int j = 0; j < 4; j++) b[j] = Bs[kq][tx * 4 + j];
#pragma unroll
            for (int i = 0; i < 4; i++)
#pragma unroll
                for (int j = 0; j < 4; j++) acc[i][j] += a[i] * b[j];
        }
        __syncthreads();
    }
#pragma unroll
    for (int i = 0; i < 4; i++)
#pragma unroll
        for (int j = 0; j < 4; j++)
            C[(m0 + ty * 4 + i) * ldc + n0 + tx * 4 + j] = alpha * acc[i][j];
}

// ---------------- score-net stage 2 ----------------
__global__ void score_stage2(const float* __restrict__ hidden,
                             const float* __restrict__ sb1,
                             const float* __restrict__ sw2,
                             const float* __restrict__ sb2,
                             float* __restrict__ out, int nrows)
{
    int warp = (blockIdx.x * blockDim.x + threadIdx.x) >> 5;
    int lane = threadIdx.x & 31;
    if (warp >= nrows) return;
    const float4 hv = ((const float4*)(hidden + (long)warp * 128))[lane];
    const float4 b1 = ((const float4*)sb1)[lane];
    const float4 w2 = ((const float4*)sw2)[lane];
    float s = fmaxf(hv.x + b1.x, 0.f) * w2.x
            + fmaxf(hv.y + b1.y, 0.f) * w2.y
            + fmaxf(hv.z + b1.z, 0.f) * w2.z
            + fmaxf(hv.w + b1.w, 0.f) * w2.w;
#pragma unroll
    for (int o = 16; o > 0; o >>= 1) s += __shfl_xor_sync(0xFFFFFFFFu, s, o);
    if (lane == 0) out[warp] = s + sb2[0];
}

// ---------------- sparsek projection + exact top-128 ----------------
__device__ __forceinline__ unsigned enc_desc(float v) {
    unsigned b = __float_as_uint(v);
    unsigned o = (b & 0x80000000u) ? ~b : (b | 0x80000000u);
    return ~o;
}
__device__ __forceinline__ float dec_desc(unsigned d) {
    unsigned o = ~d;
    unsigned b = (o & 0x80000000u) ? (o ^ 0x80000000u) : ~o;
    return __uint_as_float(b);
}

__global__ __launch_bounds__(1024) void sparsek_topk(const float* __restrict__ scores,
                                                     int* __restrict__ out_idx)
{
    __shared__ unsigned long long key[SS];
    __shared__ unsigned char flag[SS];
    __shared__ int nposs;
    int bh  = blockIdx.x;
    int tid = threadIdx.x;
    const float* s = scores + (long)bh * SS;

    for (int i = tid; i < SS; i += 1024)
        key[i] = ((unsigned long long)enc_desc(s[i]) << 32) | (unsigned)i;
    __syncthreads();

    for (int k = 2; k <= SS; k <<= 1) {
        for (int j = k >> 1; j > 0; j >>= 1) {
            for (int i = tid; i < SS; i += 1024) {
                int ixj = i ^ j;
                if (ixj > i) {
                    bool up = ((i & k) == 0);
                    unsigned long long a = key[i], b = key[ixj];
                    if ((a > b) == up) { key[i] = b; key[ixj] = a; }
                }
            }
            __syncthreads();
        }
    }

    if (tid == 0) {
        float cs = 0.f;
        int rho = 0;
        for (int r = 0; r < SS; r++) {
            float v = dec_desc((unsigned)(key[r] >> 32));
            cs += v;
            float thr = (cs - (float)KSEL) / (float)(r + 1);
            if (v > thr) rho++;
        }
        if (rho < 1) rho = 1;
        float cs2 = 0.f;
        for (int r = 0; r < rho; r++) cs2 += dec_desc((unsigned)(key[r] >> 32));
        float tau = (cs2 - (float)KSEL) / (float)rho;
        int npos = 0;
        for (int r = 0; r < SS; r++)
            if (dec_desc((unsigned)(key[r] >> 32)) > tau) npos++;
        nposs = npos;
    }
    __syncthreads();

    int npos = nposs;
    if (npos >= KSEL) {
        if (tid < KSEL)
            out_idx[bh * KSEL + tid] = (int)(key[tid] & 0xFFFFFFFFu);
    } else {
        if (tid < npos)
            out_idx[bh * KSEL + tid] = (int)(key[tid] & 0xFFFFFFFFu);
        for (int i = tid; i < SS; i += 1024) flag[i] = 0;
        __syncthreads();
        for (int i = tid; i < npos; i += 1024)
            flag[key[i] & 0xFFFFFFFFu] = 1;
        __syncthreads();
        if (tid == 0) {
            int cnt = npos;
            for (int i = 0; i < SS && cnt < KSEL; i++)
                if (!flag[i]) out_idx[bh * KSEL + cnt++] = i;
        }
    }
}

// ---------------- gather selected K / V^T ----------------
__global__ void gather_kv(const float* __restrict__ Kg, const float* __restrict__ Vg,
                          const int* __restrict__ idx,
                          float* __restrict__ ksel, float* __restrict__ vselT)
{
    int bh = blockIdx.x >> 7;
    int j  = blockIdx.x & 127;
    int d  = threadIdx.x;
    int b  = bh >> 4, h = bh & 15;
    int row = idx[bh * KSEL + j];
    long src = ((long)(b * SS + row)) * HH + (long)h * HDIM + d;
    ksel [(long)bh * (KSEL*HDIM) + (long)j * HDIM + d] = Kg[src];
    vselT[(long)bh * (KSEL*HDIM) + (long)d * KSEL + j] = Vg[src];
}

// ---------------- softmax over rows of 128 ----------------
__global__ void softmax128(float* __restrict__ p, int nrows)
{
    int warp = (blockIdx.x * blockDim.x + threadIdx.x) >> 5;
    int lane = threadIdx.x & 31;
    if (warp >= nrows) return;
    float4* row = (float4*)(p + (long)warp * 128);
    float4 v = row[lane];
    float m = fmaxf(fmaxf(v.x, v.y), fmaxf(v.z, v.w));
#pragma unroll
    for (int o = 16; o > 0; o >>= 1) m = fmaxf(m, __shfl_xor_sync(0xFFFFFFFFu, m, o));
    v.x = expf(v.x - m); v.y = expf(v.y - m);
    v.z = expf(v.z - m); v.w = expf(v.w - m);
    float sum = v.x + v.y + v.z + v.w;
#pragma unroll
    for (int o = 16; o > 0; o >>= 1) sum += __shfl_xor_sync(0xFFFFFFFFu, sum, o);
    float inv = 1.0f / sum;
    v.x *= inv; v.y *= inv; v.z *= inv; v.w *= inv;
    row[lane] = v;
}

// ---------------- launch ----------------
extern "C" void kernel_launch(void* const* d_in, const int* in_sizes, int n_in,
                              void* d_out, int out_size)
{
    const float* x   = (const float*)d_in[0];
    const float* wq  = (const float*)d_in[1];
    const float* wk  = (const float*)d_in[2];
    const float* wv  = (const float*)d_in[3];
    const float* wo  = (const float*)d_in[4];
    const float* sw1 = (const float*)d_in[5];
    const float* sb1 = (const float*)d_in[6];
    const float* sw2 = (const float*)d_in[7];
    const float* sb2 = (const float*)d_in[8];
    float* out = (float*)d_out;

    float *pQ, *pK, *pV, *pTmp, *pO, *pScores, *pKsel, *pVselT;
    int* pIdx;
    __half *pXhi, *pXlo, *pWhi, *pWlo;
    cudaGetSymbolAddress((void**)&pQ,      gQ);
    cudaGetSymbolAddress((void**)&pK,      gK);
    cudaGetSymbolAddress((void**)&pV,      gV);
    cudaGetSymbolAddress((void**)&pTmp,    gTmp);
    cudaGetSymbolAddress((void**)&pO,      gO);
    cudaGetSymbolAddress((void**)&pScores, gScores);
    cudaGetSymbolAddress((void**)&pIdx,    gIdx);
    cudaGetSymbolAddress((void**)&pKsel,   gKsel);
    cudaGetSymbolAddress((void**)&pVselT,  gVselT);
    cudaGetSymbolAddress((void**)&pXhi,    gXhi);
    cudaGetSymbolAddress((void**)&pXlo,    gXlo);
    cudaGetSymbolAddress((void**)&pWhi,    gWhi);
    cudaGetSymbolAddress((void**)&pWlo,    gWlo);

    const int HG_SMEM = 2 * STAGE_B;   // 81920; epilogue reuses (128*132*4 = 67584)
    cudaFuncSetAttribute(hgemm_split, cudaFuncAttributeMaxDynamicSharedMemorySize, HG_SMEM);

    const long sBH  = (long)SS * HH;
    const long sHd  = HDIM;
    const long sTb  = (long)NHEADS * SS * HDIM;
    const long sTh  = (long)SS * HDIM;
    const long sSelb = (long)NHEADS * KSEL * HDIM;
    const long sSelh = (long)KSEL * HDIM;

    dim3 gBig(HH / 128, NROWS / 128);     // (16, 64)
    dim3 gatt(HDIM / TS, SS / TS, NBH);   // (2, 64, 32)

    // ---- split X once ----
    split2h<<<(int)((ROWHID + 255) / 256), 256>>>(x, pXhi, pXlo, ROWHID);

    // ---- Q = X @ wq^T ----
    split2h<<<(int)((WN + 255) / 256), 256>>>(wq, pWhi, pWlo, WN);
    hgemm_split<<<gBig, 256, HG_SMEM>>>(pXhi, pXlo, pWhi, pWlo, pQ, HH, HH, HH, HH);
    // ---- K = X @ wk^T ----
    split2h<<<(int)((WN + 255) / 256), 256>>>(wk, pWhi, pWlo, WN);
    hgemm_split<<<gBig, 256, HG_SMEM>>>(pXhi, pXlo, pWhi, pWlo, pK, HH, HH, HH, HH);
    // ---- V = X @ wv^T ----
    split2h<<<(int)((WN + 255) / 256), 256>>>(wv, pWhi, pWlo, WN);
    hgemm_split<<<gBig, 256, HG_SMEM>>>(pXhi, pXlo, pWhi, pWlo, pV, HH, HH, HH, HH);

    // ---- score-net hidden = K_head @ sw1^T (fp32) ----
    sgemm_nt<<<gatt, 256>>>(pK, HH, sBH, sHd,
                            sw1, HDIM, 0, 0,
                            pTmp, HDIM, sTb, sTh,
                            SS, HDIM, HDIM, 1.0f);
    score_stage2<<<(NBH * SS) / 8, 256>>>(pTmp, sb1, sw2, sb2, pScores, NBH * SS);
    sparsek_topk<<<NBH, 1024>>>(pScores, pIdx);
    gather_kv<<<NBH * KSEL, HDIM>>>(pK, pV, pIdx, pKsel, pVselT);

    // ---- attention (fp32) ----
    const float scale = 0.08838834764831845f;
    sgemm_nt<<<gatt, 256>>>(pQ, HH, sBH, sHd,
                            pKsel, HDIM, sSelb, sSelh,
                            pTmp, HDIM, sTb, sTh,
                            SS, KSEL, HDIM, scale);
    softmax128<<<(NBH * SS) / 8, 256>>>(pTmp, NBH * SS);
    sgemm_nt<<<gatt, 256>>>(pTmp, HDIM, sTb, sTh,
                            pVselT, KSEL, sSelb, sSelh,
                            pO, HH, sBH, sHd,
                            SS, HDIM, KSEL, 1.0f);

    // ---- out = O @ wo^T ----
    split2h<<<(int)((ROWHID + 255) / 256), 256>>>(pO, pXhi, pXlo, ROWHID);
    split2h<<<(int)((WN + 255) / 256), 256>>>(wo, pWhi, pWlo, WN);
    hgemm_split<<<gBig, 256, HG_SMEM>>>(pXhi, pXlo, pWhi, pWlo, out, HH, HH, HH, HH);
}